// round 12
// baseline (speedup 1.0000x reference)
#include <cuda_runtime.h>
#include <cuda_bf16.h>
#include <math.h>
#include <stdint.h>

// Problem constants
#define BB 2
#define SS 2048
#define DD 1024
#define HH 16
#define DKK 64
#define MM (BB * SS)          // 4096
#define SCALE 0.125f          // 1/sqrt(64)

// Scratch (allocation-free rule: __device__ globals)
__device__ float g_Q[BB * HH * SS * DKK];   // [B,H,S,DK] fp32 (pre-RoPE)
__device__ float g_K[BB * HH * SS * DKK];
__device__ __nv_bfloat16 g_Qhi[BB * HH * SS * DKK];  // post-RoPE hi/lo
__device__ __nv_bfloat16 g_Qlo[BB * HH * SS * DKK];
__device__ __nv_bfloat16 g_Khi[BB * HH * SS * DKK];
__device__ __nv_bfloat16 g_Klo[BB * HH * SS * DKK];
__device__ __nv_bfloat16 g_Vthi[BB * HH * DKK * SS]; // V transposed [b,h,dk,s]
__device__ __nv_bfloat16 g_Vtlo[BB * HH * DKK * SS];
__device__ __nv_bfloat16 g_xhi[MM * DD];
__device__ __nv_bfloat16 g_xlo[MM * DD];
__device__ __nv_bfloat16 g_ahi[MM * DD];    // attention output hi/lo (O-proj input)
__device__ __nv_bfloat16 g_alo[MM * DD];
__device__ __nv_bfloat16 g_whi[3 * DD * DD]; // W^T hi, 3 sections (QKV fused)
__device__ __nv_bfloat16 g_wlo[3 * DD * DD];

// ---------------------------------------------------------------------------
// Helpers
// ---------------------------------------------------------------------------
__device__ __forceinline__ uint32_t s2u(const void* p) {
    uint32_t a;
    asm("{ .reg .u64 t; cvta.to.shared.u64 t, %1; cvt.u32.u64 %0, t; }"
        : "=r"(a) : "l"(p));
    return a;
}
__device__ __forceinline__ void cp16(uint32_t dst, const void* src) {
    asm volatile("cp.async.cg.shared.global [%0], [%1], 16;" :: "r"(dst), "l"(src));
}
#define CP_COMMIT() asm volatile("cp.async.commit_group;" ::: "memory")
#define CP_WAIT1()  asm volatile("cp.async.wait_group 1;" ::: "memory")

__device__ __forceinline__ void mma16816(float* c, const uint32_t* a, const uint32_t* b)
{
    asm volatile(
        "mma.sync.aligned.m16n8k16.row.col.f32.bf16.bf16.f32 "
        "{%0,%1,%2,%3}, {%4,%5,%6,%7}, {%8,%9}, {%0,%1,%2,%3};"
        : "+f"(c[0]), "+f"(c[1]), "+f"(c[2]), "+f"(c[3])
        : "r"(a[0]), "r"(a[1]), "r"(a[2]), "r"(a[3]), "r"(b[0]), "r"(b[1]));
}
__device__ __forceinline__ void ldsm4(uint32_t* r, uint32_t addr)
{
    asm volatile(
        "ldmatrix.sync.aligned.m8n8.x4.shared.b16 {%0,%1,%2,%3}, [%4];"
        : "=r"(r[0]), "=r"(r[1]), "=r"(r[2]), "=r"(r[3]) : "r"(addr));
}
__device__ __forceinline__ uint32_t pack_bf2(float a, float b) {
    __nv_bfloat162 t = __floats2bfloat162_rn(a, b);
    return *(uint32_t*)&t;
}

// ---------------------------------------------------------------------------
// fp32 -> bf16 hi/lo split (elementwise)
// ---------------------------------------------------------------------------
__global__ __launch_bounds__(256) void convert_hl(
    const float* __restrict__ src, __nv_bfloat16* __restrict__ hi,
    __nv_bfloat16* __restrict__ lo, int n)
{
    int i = (blockIdx.x * blockDim.x + threadIdx.x) * 4;
    if (i >= n) return;
    float4 v = *(const float4*)(src + i);
    float f[4] = {v.x, v.y, v.z, v.w};
    __nv_bfloat16 h[4], l[4];
#pragma unroll
    for (int j = 0; j < 4; ++j) {
        h[j] = __float2bfloat16(f[j]);
        l[j] = __float2bfloat16(f[j] - __bfloat162float(h[j]));
    }
    *(uint2*)(hi + i) = *(uint2*)h;
    *(uint2*)(lo + i) = *(uint2*)l;
}

// ---------------------------------------------------------------------------
// W[k][n] -> Wt[n][k] bf16 hi/lo (tiled transpose), grid.z = section
// ---------------------------------------------------------------------------
__global__ __launch_bounds__(256) void convert_w3_t(
    const float* __restrict__ W0, const float* __restrict__ W1,
    const float* __restrict__ W2)
{
    __shared__ float t[32][33];
    const int sec = blockIdx.z;
    const float* W = (sec == 0) ? W0 : (sec == 1) ? W1 : W2;
    __nv_bfloat16* hi = g_whi + (size_t)sec * DD * DD;
    __nv_bfloat16* lo = g_wlo + (size_t)sec * DD * DD;
    int tx = threadIdx.x, ty = threadIdx.y;
    int kin = blockIdx.y * 32;
    int nin = blockIdx.x * 32;
#pragma unroll
    for (int j = 0; j < 4; ++j)
        t[ty + j * 8][tx] = W[(size_t)(kin + ty + j * 8) * DD + nin + tx];
    __syncthreads();
#pragma unroll
    for (int j = 0; j < 4; ++j) {
        float v = t[tx][ty + j * 8];
        __nv_bfloat16 h = __float2bfloat16(v);
        __nv_bfloat16 l = __float2bfloat16(v - __bfloat162float(h));
        size_t o = (size_t)(nin + ty + j * 8) * DD + kin + tx;
        hi[o] = h;
        lo[o] = l;
    }
}

// ---------------------------------------------------------------------------
// bf16x3 HMMA GEMM, CTA 128x256, 8 warps of 64x64, BK=32, ldmatrix frags,
// cp.async double buffer.
// Stage: Ahi(10240) Alo(10240) Bhi(20480) Blo(20480) = 61440; x2 = 122880.
// QKV=true: fused N=3072; epilogue by section (Q/K fp32 head layout, V bf16^T).
// QKV=false: fp32 out [m][n] + bias.
// ---------------------------------------------------------------------------
#define GEMM_SMEM 122880

template <bool QKV>
__global__ __launch_bounds__(256, 1) void mma_gemm(
    const __nv_bfloat16* __restrict__ Ahi, const __nv_bfloat16* __restrict__ Alo,
    const __nv_bfloat16* __restrict__ Bhi, const __nv_bfloat16* __restrict__ Blo,
    const float* __restrict__ b0p, const float* __restrict__ b1p,
    const float* __restrict__ b2p,
    float* __restrict__ outQ, float* __restrict__ outK)
{
    extern __shared__ char smem[];
    const uint32_t smem_u = s2u(smem);
    const int tid = threadIdx.x;
    const int lane = tid & 31;
    const int wid = tid >> 5;
    const int g = lane >> 2;
    const int tg = lane & 3;
    const int warp_m = wid & 1;    // 2 x 64 rows
    const int warp_n = wid >> 1;   // 4 x 64 cols
    const int n0 = blockIdx.x * 256;
    const int m0 = blockIdx.y * 128;

    float acc[4][8][4] = {};

    // ldmatrix per-lane row/col offsets (shared formula for A and B)
    const int lrow = (((lane >> 3) & 1) << 3) + (lane & 7);
    const int lcol = (lane >> 4) << 4;

    auto load_stage = [&](int st, int kc) {
        const int k0 = kc * 32;
        const uint32_t sb = smem_u + st * 61440;
        // A: 128 rows x 32 bf16, hi+lo. 512 vec16 each -> 2/thread.
#pragma unroll
        for (int it = 0; it < 2; ++it) {
            int v = it * 256 + tid;
            int r = v >> 2, c = v & 3;
            uint32_t d = sb + r * 80 + c * 16;
            size_t gsrc = (size_t)(m0 + r) * DD + k0 + c * 8;
            cp16(d, Ahi + gsrc);
            cp16(d + 10240, Alo + gsrc);
        }
        // B: 256 n-rows x 32 bf16, hi+lo. 1024 vec16 each -> 4/thread.
#pragma unroll
        for (int it = 0; it < 4; ++it) {
            int v = it * 256 + tid;
            int r = v >> 2, c = v & 3;
            uint32_t d = sb + 20480 + r * 80 + c * 16;
            size_t gsrc = (size_t)(n0 + r) * DD + k0 + c * 8;
            cp16(d, Bhi + gsrc);
            cp16(d + 20480, Blo + gsrc);
        }
    };

    load_stage(0, 0); CP_COMMIT();
    load_stage(1, 1); CP_COMMIT();

    for (int kc = 0; kc < 32; ++kc) {
        const int st = kc & 1;
        CP_WAIT1();
        __syncthreads();

        const uint32_t sA = smem_u + st * 61440 + (warp_m * 64 + lrow) * 80 + lcol;
        const uint32_t sB = smem_u + st * 61440 + 20480 + (warp_n * 64 + lrow) * 80 + lcol;

#pragma unroll
        for (int ks = 0; ks < 2; ++ks) {
            const int kb = ks * 32;

            uint32_t ah[4][4], al[4][4];
#pragma unroll
            for (int mt = 0; mt < 4; ++mt) {
                ldsm4(ah[mt], sA + mt * (16 * 80) + kb);
                ldsm4(al[mt], sA + 10240 + mt * (16 * 80) + kb);
            }
            // B: 4 pairs x (hi,lo); x4 gives {b[2p][0], b[2p+1][0], b[2p][1], b[2p+1][1]}
            uint32_t bh[8][2], bl[8][2];
#pragma unroll
            for (int p = 0; p < 4; ++p) {
                uint32_t r4[4];
                ldsm4(r4, sB + p * (16 * 80) + kb);
                bh[2 * p][0] = r4[0]; bh[2 * p + 1][0] = r4[1];
                bh[2 * p][1] = r4[2]; bh[2 * p + 1][1] = r4[3];
                ldsm4(r4, sB + 20480 + p * (16 * 80) + kb);
                bl[2 * p][0] = r4[0]; bl[2 * p + 1][0] = r4[1];
                bl[2 * p][1] = r4[2]; bl[2 * p + 1][1] = r4[3];
            }

            // split-outermost: same-acc MMAs are 32 apart
#pragma unroll
            for (int mt = 0; mt < 4; ++mt)
#pragma unroll
                for (int nt = 0; nt < 8; ++nt)
                    mma16816(acc[mt][nt], ah[mt], bh[nt]);
#pragma unroll
            for (int mt = 0; mt < 4; ++mt)
#pragma unroll
                for (int nt = 0; nt < 8; ++nt)
                    mma16816(acc[mt][nt], ah[mt], bl[nt]);
#pragma unroll
            for (int mt = 0; mt < 4; ++mt)
#pragma unroll
                for (int nt = 0; nt < 8; ++nt)
                    mma16816(acc[mt][nt], al[mt], bh[nt]);
        }

        __syncthreads();
        if (kc + 2 < 32) load_stage(st, kc + 2);
        CP_COMMIT();
    }

    // ---- epilogue ----
    const int sec = QKV ? (n0 >> 10) : 0;   // uniform per CTA (256 | 1024)
    const float* bias = QKV ? ((sec == 0) ? b0p : (sec == 1) ? b1p : b2p) : b0p;

#pragma unroll
    for (int mt = 0; mt < 4; ++mt) {
        const int m = m0 + warp_m * 64 + mt * 16 + g;
#pragma unroll
        for (int nt = 0; nt < 8; ++nt) {
            const int nc = n0 + warp_n * 64 + nt * 8 + tg * 2;
            const int nl = QKV ? (nc & 1023) : nc;
            const float bv0 = __ldg(bias + nl), bv1 = __ldg(bias + nl + 1);
            float v00 = acc[mt][nt][0] + bv0, v01 = acc[mt][nt][1] + bv1;
            float v10 = acc[mt][nt][2] + bv0, v11 = acc[mt][nt][3] + bv1;
            if (QKV) {
                const int h = nl >> 6, dk = nl & 63;
                const int b_ = m >> 11, s = m & 2047;
                if (sec < 2) {
                    float* dst = (sec == 0) ? outQ : outK;
                    size_t base = (((size_t)(b_ * HH + h) * SS) + s) * DKK + dk;
                    *(float2*)(dst + base) = make_float2(v00, v01);
                    *(float2*)(dst + base + 8 * DKK) = make_float2(v10, v11);
                } else {
                    size_t base = (((size_t)(b_ * HH + h) * DKK) + dk) * SS + s;
                    float vv[4] = {v00, v01, v10, v11};
                    size_t off[4] = {base, base + SS, base + 8, base + SS + 8};
#pragma unroll
                    for (int e = 0; e < 4; ++e) {
                        __nv_bfloat16 hh = __float2bfloat16(vv[e]);
                        g_Vthi[off[e]] = hh;
                        g_Vtlo[off[e]] = __float2bfloat16(vv[e] - __bfloat162float(hh));
                    }
                }
            } else {
                *(float2*)(outQ + (size_t)m * DD + nc) = make_float2(v00, v01);
                *(float2*)(outQ + (size_t)(m + 8) * DD + nc) = make_float2(v10, v11);
            }
        }
    }
}

// ---------------------------------------------------------------------------
// RoPE: read fp32 g_Q/g_K, rotate, write bf16 hi/lo Q/K.
// ---------------------------------------------------------------------------
__global__ __launch_bounds__(256) void rope_kernel(const int* __restrict__ pos)
{
    __shared__ float invs[32];
    if (threadIdx.x < 32)
        invs[threadIdx.x] = (float)exp(-(double)threadIdx.x * 0.28782313662425575);
    __syncthreads();

    int idx = blockIdx.x * blockDim.x + threadIdx.x;
    if (idx >= BB * HH * SS * (DKK / 2)) return;
    int i = idx & 31;
    int s = (idx >> 5) & 2047;
    int h = (idx >> 16) & 15;
    int b = idx >> 20;

    int p = pos[b * SS + s];
    float ang = (float)p * invs[i];
    float c, sn;
    sincosf(ang, &sn, &c);

    size_t base = (((size_t)(b * HH + h) * SS) + s) * DKK + 2 * i;
    float q0 = g_Q[base], q1 = g_Q[base + 1];
    float qr0 = q0 * c - q1 * sn;
    float qr1 = q0 * sn + q1 * c;
    float k0 = g_K[base], k1 = g_K[base + 1];
    float kr0 = k0 * c - k1 * sn;
    float kr1 = k0 * sn + k1 * c;

    __nv_bfloat162 qh = __floats2bfloat162_rn(qr0, qr1);
    *(uint32_t*)(g_Qhi + base) = *(uint32_t*)&qh;
    __nv_bfloat162 ql = __floats2bfloat162_rn(qr0 - __bfloat162float(qh.x),
                                              qr1 - __bfloat162float(qh.y));
    *(uint32_t*)(g_Qlo + base) = *(uint32_t*)&ql;
    __nv_bfloat162 kh = __floats2bfloat162_rn(kr0, kr1);
    *(uint32_t*)(g_Khi + base) = *(uint32_t*)&kh;
    __nv_bfloat162 kl = __floats2bfloat162_rn(kr0 - __bfloat162float(kh.x),
                                              kr1 - __bfloat162float(kh.y));
    *(uint32_t*)(g_Klo + base) = *(uint32_t*)&kl;
}

// ---------------------------------------------------------------------------
// Flash attention with HMMA (bf16x3 split for QK and PV). Unchanged from R10.
// ---------------------------------------------------------------------------
#define FL_PITCH 144
#define FL_TILE (64 * FL_PITCH)
#define FL_STAGE (4 * FL_TILE)
#define FL_SMEM (2 * FL_STAGE)

__global__ __launch_bounds__(128) void flash_mma()
{
    extern __shared__ char smem[];
    const int qt = (int)gridDim.x - 1 - (int)blockIdx.x;
    const int h = blockIdx.y;
    const int b = blockIdx.z;
    const int q0 = qt * 64;
    const int tid = threadIdx.x;
    const int lane = tid & 31;
    const int w = tid >> 5;
    const int g = lane >> 2;
    const int tg = lane & 3;

    const size_t bh = (size_t)(b * HH + h);
    const __nv_bfloat16* Qhi = g_Qhi + bh * SS * DKK;
    const __nv_bfloat16* Qlo = g_Qlo + bh * SS * DKK;
    const __nv_bfloat16* Khi = g_Khi + bh * SS * DKK;
    const __nv_bfloat16* Klo = g_Klo + bh * SS * DKK;
    const __nv_bfloat16* Vthi = g_Vthi + bh * DKK * SS;
    const __nv_bfloat16* Vtlo = g_Vtlo + bh * DKK * SS;

    const int qrow = q0 + w * 16 + g;
    uint32_t qh[4][4], ql[4][4];
#pragma unroll
    for (int kc = 0; kc < 4; ++kc) {
        size_t p0 = (size_t)qrow * DKK + kc * 16 + tg * 2;
        qh[kc][0] = *(const uint32_t*)(Qhi + p0);
        qh[kc][1] = *(const uint32_t*)(Qhi + p0 + 8 * DKK);
        qh[kc][2] = *(const uint32_t*)(Qhi + p0 + 8);
        qh[kc][3] = *(const uint32_t*)(Qhi + p0 + 8 * DKK + 8);
        ql[kc][0] = *(const uint32_t*)(Qlo + p0);
        ql[kc][1] = *(const uint32_t*)(Qlo + p0 + 8 * DKK);
        ql[kc][2] = *(const uint32_t*)(Qlo + p0 + 8);
        ql[kc][3] = *(const uint32_t*)(Qlo + p0 + 8 * DKK + 8);
    }

    auto load_stage = [&](int st, int t) {
        const int j0 = t * 64;
        char* sb = smem + st * FL_STAGE;
#pragma unroll
        for (int i = 0; i < 4; ++i) {
            int v = i * 128 + tid;
            int r = v >> 3, c = v & 7;
            uint32_t d = s2u(sb + r * FL_PITCH + c * 16);
            size_t ksrc = (size_t)(j0 + r) * DKK + c * 8;
            cp16(d, Khi + ksrc);
            cp16(d + FL_TILE, Klo + ksrc);
            size_t vsrc = (size_t)r * SS + j0 + c * 8;
            cp16(d + 2 * FL_TILE, Vthi + vsrc);
            cp16(d + 3 * FL_TILE, Vtlo + vsrc);
        }
    };

    float o[8][4] = {};
    float m_g = -1e30f, m_g8 = -1e30f;
    float l_g = 0.f, l_g8 = 0.f;

    const int nT = qt + 1;
    load_stage(0, 0); CP_COMMIT();
    if (nT > 1) load_stage(1, 1);
    CP_COMMIT();

    for (int t = 0; t < nT; ++t) {
        const int st = t & 1;
        CP_WAIT1();
        __syncthreads();

        const char* sK  = smem + st * FL_STAGE;
        const char* sKl = sK + FL_TILE;
        const char* sV  = sK + 2 * FL_TILE;
        const char* sVl = sK + 3 * FL_TILE;
        const int j0 = t * 64;

        float s[8][4] = {};
#pragma unroll
        for (int kc = 0; kc < 4; ++kc) {
            const int kb = kc * 32 + tg * 4;
            uint32_t kh[8][2], kl[8][2];
#pragma unroll
            for (int nf = 0; nf < 8; ++nf) {
                const char* p = sK + (nf * 8 + g) * FL_PITCH + kb;
                kh[nf][0] = *(const uint32_t*)p;
                kh[nf][1] = *(const uint32_t*)(p + 16);
                const char* p2 = sKl + (nf * 8 + g) * FL_PITCH + kb;
                kl[nf][0] = *(const uint32_t*)p2;
                kl[nf][1] = *(const uint32_t*)(p2 + 16);
            }
#pragma unroll
            for (int nf = 0; nf < 8; ++nf) {
                mma16816(s[nf], qh[kc], kh[nf]);
                mma16816(s[nf], qh[kc], kl[nf]);
                mma16816(s[nf], ql[kc], kh[nf]);
            }
        }

        const bool diag = (t == qt);
#pragma unroll
        for (int nf = 0; nf < 8; ++nf) {
#pragma unroll
            for (int e = 0; e < 4; ++e) {
                float v = s[nf][e] * SCALE;
                if (diag) {
                    int col = j0 + nf * 8 + tg * 2 + (e & 1);
                    int row = qrow + ((e >> 1) << 3);
                    if (col > row) v = -1e30f;
                }
                s[nf][e] = v;
            }
        }

        float tm_g = -1e30f, tm_g8 = -1e30f;
#pragma unroll
        for (int nf = 0; nf < 8; ++nf) {
            tm_g  = fmaxf(tm_g,  fmaxf(s[nf][0], s[nf][1]));
            tm_g8 = fmaxf(tm_g8, fmaxf(s[nf][2], s[nf][3]));
        }
        tm_g  = fmaxf(tm_g,  __shfl_xor_sync(0xffffffffu, tm_g, 1));
        tm_g  = fmaxf(tm_g,  __shfl_xor_sync(0xffffffffu, tm_g, 2));
        tm_g8 = fmaxf(tm_g8, __shfl_xor_sync(0xffffffffu, tm_g8, 1));
        tm_g8 = fmaxf(tm_g8, __shfl_xor_sync(0xffffffffu, tm_g8, 2));

        float mn_g = fmaxf(m_g, tm_g);
        float mn_g8 = fmaxf(m_g8, tm_g8);
        float alpha_g = expf(m_g - mn_g);
        float alpha_g8 = expf(m_g8 - mn_g8);
        m_g = mn_g; m_g8 = mn_g8;

        float sum_g = 0.f, sum_g8 = 0.f;
#pragma unroll
        for (int nf = 0; nf < 8; ++nf) {
            s[nf][0] = expf(s[nf][0] - mn_g);
            s[nf][1] = expf(s[nf][1] - mn_g);
            s[nf][2] = expf(s[nf][2] - mn_g8);
            s[nf][3] = expf(s[nf][3] - mn_g8);
            sum_g += s[nf][0] + s[nf][1];
            sum_g8 += s[nf][2] + s[nf][3];
        }
        sum_g  += __shfl_xor_sync(0xffffffffu, sum_g, 1);
        sum_g  += __shfl_xor_sync(0xffffffffu, sum_g, 2);
        sum_g8 += __shfl_xor_sync(0xffffffffu, sum_g8, 1);
        sum_g8 += __shfl_xor_sync(0xffffffffu, sum_g8, 2);
        l_g = l_g * alpha_g + sum_g;
        l_g8 = l_g8 * alpha_g8 + sum_g8;

#pragma unroll
        for (int nf = 0; nf < 8; ++nf) {
            o[nf][0] *= alpha_g;
            o[nf][1] *= alpha_g;
            o[nf][2] *= alpha_g8;
            o[nf][3] *= alpha_g8;
        }

#pragma unroll
        for (int kc = 0; kc < 4; ++kc) {
            uint32_t ph[4], pl[4];
            {
                const float* s0 = s[2 * kc];
                const float* s1 = s[2 * kc + 1];
                float h0 = __bfloat162float(__float2bfloat16(s0[0]));
                float h1 = __bfloat162float(__float2bfloat16(s0[1]));
                float h2 = __bfloat162float(__float2bfloat16(s0[2]));
                float h3 = __bfloat162float(__float2bfloat16(s0[3]));
                float h4 = __bfloat162float(__float2bfloat16(s1[0]));
                float h5 = __bfloat162float(__float2bfloat16(s1[1]));
                float h6 = __bfloat162float(__float2bfloat16(s1[2]));
                float h7 = __bfloat162float(__float2bfloat16(s1[3]));
                ph[0] = pack_bf2(h0, h1);
                ph[1] = pack_bf2(h2, h3);
                ph[2] = pack_bf2(h4, h5);
                ph[3] = pack_bf2(h6, h7);
                pl[0] = pack_bf2(s0[0] - h0, s0[1] - h1);
                pl[1] = pack_bf2(s0[2] - h2, s0[3] - h3);
                pl[2] = pack_bf2(s1[0] - h4, s1[1] - h5);
                pl[3] = pack_bf2(s1[2] - h6, s1[3] - h7);
            }
            const int kb = kc * 32 + tg * 4;
            uint32_t vh[8][2], vl[8][2];
#pragma unroll
            for (int nf = 0; nf < 8; ++nf) {
                const char* p = sV + (nf * 8 + g) * FL_PITCH + kb;
                vh[nf][0] = *(const uint32_t*)p;
                vh[nf][1] = *(const uint32_t*)(p + 16);
                const char* p2 = sVl + (nf * 8 + g) * FL_PITCH + kb;
                vl[nf][0] = *(const uint32_t*)p2;
                vl[nf][1] = *(const uint32_t*)(p2 + 16);
            }
#pragma unroll
            for (int nf = 0; nf < 8; ++nf) {
                mma16816(o[nf], ph, vh[nf]);
                mma16816(o[nf], ph, vl[nf]);
                mma16816(o[nf], pl, vh[nf]);
            }
        }

        __syncthreads();
        if (t + 2 < nT) load_stage(st, t + 2);
        CP_COMMIT();
    }

    const float inv_g = 1.0f / l_g;
    const float inv_g8 = 1.0f / l_g8;
#pragma unroll
    for (int nf = 0; nf < 8; ++nf) {
        const int col = h * DKK + nf * 8 + tg * 2;
        {
            float v0 = o[nf][0] * inv_g, v1 = o[nf][1] * inv_g;
            size_t addr = ((size_t)b * SS + qrow) * DD + col;
            __nv_bfloat162 hh = __floats2bfloat162_rn(v0, v1);
            *(uint32_t*)(g_ahi + addr) = *(uint32_t*)&hh;
            __nv_bfloat162 ll = __floats2bfloat162_rn(v0 - __bfloat162float(hh.x),
                                                      v1 - __bfloat162float(hh.y));
            *(uint32_t*)(g_alo + addr) = *(uint32_t*)&ll;
        }
        {
            float v0 = o[nf][2] * inv_g8, v1 = o[nf][3] * inv_g8;
            size_t addr = ((size_t)b * SS + qrow + 8) * DD + col;
            __nv_bfloat162 hh = __floats2bfloat162_rn(v0, v1);
            *(uint32_t*)(g_ahi + addr) = *(uint32_t*)&hh;
            __nv_bfloat162 ll = __floats2bfloat162_rn(v0 - __bfloat162float(hh.x),
                                                      v1 - __bfloat162float(hh.y));
            *(uint32_t*)(g_alo + addr) = *(uint32_t*)&ll;
        }
    }
}

// ---------------------------------------------------------------------------
extern "C" void kernel_launch(void* const* d_in, const int* in_sizes, int n_in,
                              void* d_out, int out_size)
{
    const float* x  = (const float*)d_in[0];
    const int*   tp = (const int*)d_in[1];
    const float* Wq = (const float*)d_in[2];
    const float* bq = (const float*)d_in[3];
    const float* Wk = (const float*)d_in[4];
    const float* bk = (const float*)d_in[5];
    const float* Wv = (const float*)d_in[6];
    const float* bv = (const float*)d_in[7];
    const float* Wo = (const float*)d_in[8];
    const float* bo = (const float*)d_in[9];
    float* out = (float*)d_out;

    float *Qp, *Kp;
    __nv_bfloat16 *xhi, *xlo, *ahi, *alo, *whi, *wlo;
    cudaGetSymbolAddress((void**)&Qp, g_Q);
    cudaGetSymbolAddress((void**)&Kp, g_K);
    cudaGetSymbolAddress((void**)&xhi, g_xhi);
    cudaGetSymbolAddress((void**)&xlo, g_xlo);
    cudaGetSymbolAddress((void**)&ahi, g_ahi);
    cudaGetSymbolAddress((void**)&alo, g_alo);
    cudaGetSymbolAddress((void**)&whi, g_whi);
    cudaGetSymbolAddress((void**)&wlo, g_wlo);

    static int attr_set = 0;
    if (!attr_set) {
        cudaFuncSetAttribute(mma_gemm<true>,
                             cudaFuncAttributeMaxDynamicSharedMemorySize, GEMM_SMEM);
        cudaFuncSetAttribute(mma_gemm<false>,
                             cudaFuncAttributeMaxDynamicSharedMemorySize, GEMM_SMEM);
        cudaFuncSetAttribute(flash_mma,
                             cudaFuncAttributeMaxDynamicSharedMemorySize, FL_SMEM);
        attr_set = 1;
    }

    const int nX = MM * DD;
    dim3 bW(32, 8);

    convert_hl<<<nX / 4 / 256, 256>>>(x, xhi, xlo, nX);
    convert_w3_t<<<dim3(32, 32, 3), bW>>>(Wq, Wk, Wv);

    // Fused QKV projection: N=3072, CTA 128x256 -> (12, 32) = 384 CTAs
    dim3 gQKV(3 * DD / 256, MM / 128);
    mma_gemm<true><<<gQKV, 256, GEMM_SMEM>>>(xhi, xlo, whi, wlo,
                                             bq, bk, bv, Qp, Kp);

    int ropeThreads = BB * HH * SS * (DKK / 2);
    rope_kernel<<<(ropeThreads + 255) / 256, 256>>>(tp);

    dim3 gFlash(SS / 64, HH, BB);
    flash_mma<<<gFlash, 128, FL_SMEM>>>();

    // O projection (weight buffer section 0): (4, 32) = 128 CTAs
    convert_w3_t<<<dim3(32, 32, 1), bW>>>(Wo, Wo, Wo);
    dim3 gO(DD / 256, MM / 128);
    mma_gemm<false><<<gO, 256, GEMM_SMEM>>>(ahi, alo, whi, wlo,
                                            bo, bo, bo, out, nullptr);
}

// round 15
// speedup vs baseline: 1.0132x; 1.0132x over previous
#include <cuda_runtime.h>
#include <cuda_bf16.h>
#include <math.h>
#include <stdint.h>

// Problem constants
#define BB 2
#define SS 2048
#define DD 1024
#define HH 16
#define DKK 64
#define MM (BB * SS)          // 4096
#define SCALE 0.125f          // 1/sqrt(64)

// Scratch (allocation-free rule: __device__ globals)
__device__ float g_Q[BB * HH * SS * DKK];   // [B,H,S,DK] fp32 (pre-RoPE)
__device__ float g_K[BB * HH * SS * DKK];
__device__ __nv_bfloat16 g_Qhi[BB * HH * SS * DKK];  // post-RoPE hi/lo
__device__ __nv_bfloat16 g_Qlo[BB * HH * SS * DKK];
__device__ __nv_bfloat16 g_Khi[BB * HH * SS * DKK];
__device__ __nv_bfloat16 g_Klo[BB * HH * SS * DKK];
__device__ __nv_bfloat16 g_Vthi[BB * HH * DKK * SS]; // V transposed [b,h,dk,s]
__device__ __nv_bfloat16 g_Vtlo[BB * HH * DKK * SS];
__device__ __nv_bfloat16 g_xhi[MM * DD];
__device__ __nv_bfloat16 g_xlo[MM * DD];
__device__ __nv_bfloat16 g_ahi[MM * DD];    // attention output hi/lo (O-proj input)
__device__ __nv_bfloat16 g_alo[MM * DD];
__device__ __nv_bfloat16 g_whi[4 * DD * DD]; // W^T hi: secs 0..2 = QKV, 3 = O
__device__ __nv_bfloat16 g_wlo[4 * DD * DD];

// ---------------------------------------------------------------------------
// Helpers
// ---------------------------------------------------------------------------
__device__ __forceinline__ uint32_t s2u(const void* p) {
    uint32_t a;
    asm("{ .reg .u64 t; cvta.to.shared.u64 t, %1; cvt.u32.u64 %0, t; }"
        : "=r"(a) : "l"(p));
    return a;
}
__device__ __forceinline__ void cp16(uint32_t dst, const void* src) {
    asm volatile("cp.async.cg.shared.global [%0], [%1], 16;" :: "r"(dst), "l"(src));
}
#define CP_COMMIT() asm volatile("cp.async.commit_group;" ::: "memory")
#define CP_WAIT1()  asm volatile("cp.async.wait_group 1;" ::: "memory")

__device__ __forceinline__ void mma16816(float* c, const uint32_t* a, const uint32_t* b)
{
    asm volatile(
        "mma.sync.aligned.m16n8k16.row.col.f32.bf16.bf16.f32 "
        "{%0,%1,%2,%3}, {%4,%5,%6,%7}, {%8,%9}, {%0,%1,%2,%3};"
        : "+f"(c[0]), "+f"(c[1]), "+f"(c[2]), "+f"(c[3])
        : "r"(a[0]), "r"(a[1]), "r"(a[2]), "r"(a[3]), "r"(b[0]), "r"(b[1]));
}
__device__ __forceinline__ void ldsm4(uint32_t* r, uint32_t addr)
{
    asm volatile(
        "ldmatrix.sync.aligned.m8n8.x4.shared.b16 {%0,%1,%2,%3}, [%4];"
        : "=r"(r[0]), "=r"(r[1]), "=r"(r[2]), "=r"(r[3]) : "r"(addr));
}
__device__ __forceinline__ uint32_t pack_bf2(float a, float b) {
    __nv_bfloat162 t = __floats2bfloat162_rn(a, b);
    return *(uint32_t*)&t;
}

// ---------------------------------------------------------------------------
// fp32 -> bf16 hi/lo split (elementwise)
// ---------------------------------------------------------------------------
__global__ __launch_bounds__(256) void convert_hl(
    const float* __restrict__ src, __nv_bfloat16* __restrict__ hi,
    __nv_bfloat16* __restrict__ lo, int n)
{
    int i = (blockIdx.x * blockDim.x + threadIdx.x) * 4;
    if (i >= n) return;
    float4 v = *(const float4*)(src + i);
    float f[4] = {v.x, v.y, v.z, v.w};
    __nv_bfloat16 h[4], l[4];
#pragma unroll
    for (int j = 0; j < 4; ++j) {
        h[j] = __float2bfloat16(f[j]);
        l[j] = __float2bfloat16(f[j] - __bfloat162float(h[j]));
    }
    *(uint2*)(hi + i) = *(uint2*)h;
    *(uint2*)(lo + i) = *(uint2*)l;
}

// ---------------------------------------------------------------------------
// W[k][n] -> Wt[n][k] bf16 hi/lo (tiled transpose), grid.z = section 0..3
// ---------------------------------------------------------------------------
__global__ __launch_bounds__(256) void convert_w4_t(
    const float* __restrict__ W0, const float* __restrict__ W1,
    const float* __restrict__ W2, const float* __restrict__ W3)
{
    __shared__ float t[32][33];
    const int sec = blockIdx.z;
    const float* W = (sec == 0) ? W0 : (sec == 1) ? W1 : (sec == 2) ? W2 : W3;
    __nv_bfloat16* hi = g_whi + (size_t)sec * DD * DD;
    __nv_bfloat16* lo = g_wlo + (size_t)sec * DD * DD;
    int tx = threadIdx.x, ty = threadIdx.y;
    int kin = blockIdx.y * 32;
    int nin = blockIdx.x * 32;
#pragma unroll
    for (int j = 0; j < 4; ++j)
        t[ty + j * 8][tx] = W[(size_t)(kin + ty + j * 8) * DD + nin + tx];
    __syncthreads();
#pragma unroll
    for (int j = 0; j < 4; ++j) {
        float v = t[tx][ty + j * 8];
        __nv_bfloat16 h = __float2bfloat16(v);
        __nv_bfloat16 l = __float2bfloat16(v - __bfloat162float(h));
        size_t o = (size_t)(nin + ty + j * 8) * DD + kin + tx;
        hi[o] = h;
        lo[o] = l;
    }
}

// ---------------------------------------------------------------------------
// bf16x3 HMMA GEMM, CTA 128x128, 8 warps (2x4 -> 64x32 each), BK=32,
// ldmatrix fragment loads, cp.async double buffer, 2 CTAs/SM.
// QKV=true: fused N=3072; epilogue by section (Q/K fp32 head layout, V bf16^T).
// QKV=false: fp32 out [m][n] + bias (weight section 3).
// ---------------------------------------------------------------------------
#define GEMM_SMEM 81920

template <bool QKV>
__global__ __launch_bounds__(256, 2) void mma_gemm(
    const __nv_bfloat16* __restrict__ Ahi, const __nv_bfloat16* __restrict__ Alo,
    const __nv_bfloat16* __restrict__ Bhi, const __nv_bfloat16* __restrict__ Blo,
    const float* __restrict__ b0p, const float* __restrict__ b1p,
    const float* __restrict__ b2p,
    float* __restrict__ outQ, float* __restrict__ outK)
{
    extern __shared__ char smem[];
    const uint32_t smem_u = s2u(smem);
    const int tid = threadIdx.x;
    const int lane = tid & 31;
    const int wid = tid >> 5;
    const int g = lane >> 2;
    const int tg = lane & 3;
    const int warp_m = wid & 1;
    const int warp_n = wid >> 1;
    const int n0 = blockIdx.x * 128;
    const int m0 = blockIdx.y * 128;

    float acc[4][4][4] = {};

    const int r_ = tid >> 2, c4 = tid & 3;

    // ldmatrix per-lane addressing: row = lane % 16, col-half = lane / 16
    const int lrow = lane & 15;
    const int lcol = (lane >> 4) << 4;   // 0 or 16 bytes

    auto load_stage = [&](int st, int kc) {
        const int k0 = kc * 32;
        const uint32_t sb = smem_u + st * 40960;
        {
            uint32_t d = sb + r_ * 80 + c4 * 16;
            size_t gsrc = (size_t)(m0 + r_) * DD + k0 + c4 * 8;
            cp16(d, Ahi + gsrc);
            cp16(d + 10240, Alo + gsrc);
            d += 64 * 80;  gsrc += (size_t)64 * DD;
            cp16(d, Ahi + gsrc);
            cp16(d + 10240, Alo + gsrc);
        }
        {
            uint32_t d = sb + 20480 + r_ * 80 + c4 * 16;
            size_t gsrc = (size_t)(n0 + r_) * DD + k0 + c4 * 8;
            cp16(d, Bhi + gsrc);
            cp16(d + 10240, Blo + gsrc);
            d += 64 * 80;  gsrc += (size_t)64 * DD;
            cp16(d, Bhi + gsrc);
            cp16(d + 10240, Blo + gsrc);
        }
    };

    load_stage(0, 0); CP_COMMIT();
    load_stage(1, 1); CP_COMMIT();

    for (int kc = 0; kc < 32; ++kc) {
        const int st = kc & 1;
        CP_WAIT1();
        __syncthreads();

        const uint32_t sA = smem_u + st * 40960 + (warp_m * 64 + lrow) * 80 + lcol;
        const uint32_t sB = smem_u + st * 40960 + 20480 + (warp_n * 32 + lrow) * 80 + lcol;

#pragma unroll
        for (int ks = 0; ks < 2; ++ks) {
            const int kb = ks * 32;

            uint32_t ah[4][4], al[4][4];
#pragma unroll
            for (int mt = 0; mt < 4; ++mt) {
                ldsm4(ah[mt], sA + mt * (16 * 80) + kb);
                ldsm4(al[mt], sA + 10240 + mt * (16 * 80) + kb);
            }
            uint32_t bh[4][2], bl[4][2];
#pragma unroll
            for (int p = 0; p < 2; ++p) {
                uint32_t r4[4];
                ldsm4(r4, sB + p * (16 * 80) + kb);
                bh[2 * p][0] = r4[0]; bh[2 * p + 1][0] = r4[1];
                bh[2 * p][1] = r4[2]; bh[2 * p + 1][1] = r4[3];
                ldsm4(r4, sB + 10240 + p * (16 * 80) + kb);
                bl[2 * p][0] = r4[0]; bl[2 * p + 1][0] = r4[1];
                bl[2 * p][1] = r4[2]; bl[2 * p + 1][1] = r4[3];
            }

#pragma unroll
            for (int mt = 0; mt < 4; ++mt)
#pragma unroll
                for (int nt = 0; nt < 4; ++nt)
                    mma16816(acc[mt][nt], ah[mt], bh[nt]);
#pragma unroll
            for (int mt = 0; mt < 4; ++mt)
#pragma unroll
                for (int nt = 0; nt < 4; ++nt)
                    mma16816(acc[mt][nt], ah[mt], bl[nt]);
#pragma unroll
            for (int mt = 0; mt < 4; ++mt)
#pragma unroll
                for (int nt = 0; nt < 4; ++nt)
                    mma16816(acc[mt][nt], al[mt], bh[nt]);
        }

        __syncthreads();
        if (kc + 2 < 32) load_stage(st, kc + 2);
        CP_COMMIT();
    }

    // ---- epilogue ----
    const int sec = QKV ? (n0 >> 10) : 0;   // uniform per CTA
    const float* bias = QKV ? ((sec == 0) ? b0p : (sec == 1) ? b1p : b2p) : b0p;

#pragma unroll
    for (int mt = 0; mt < 4; ++mt) {
        const int m = m0 + warp_m * 64 + mt * 16 + g;
#pragma unroll
        for (int nt = 0; nt < 4; ++nt) {
            const int nc = n0 + warp_n * 32 + nt * 8 + tg * 2;
            const int nl = QKV ? (nc & 1023) : nc;
            const float bv0 = __ldg(bias + nl), bv1 = __ldg(bias + nl + 1);
            float v00 = acc[mt][nt][0] + bv0, v01 = acc[mt][nt][1] + bv1;
            float v10 = acc[mt][nt][2] + bv0, v11 = acc[mt][nt][3] + bv1;
            if (QKV) {
                const int h = nl >> 6, dk = nl & 63;
                const int b_ = m >> 11, s = m & 2047;
                if (sec < 2) {
                    float* dst = (sec == 0) ? outQ : outK;
                    size_t base = (((size_t)(b_ * HH + h) * SS) + s) * DKK + dk;
                    *(float2*)(dst + base) = make_float2(v00, v01);
                    *(float2*)(dst + base + 8 * DKK) = make_float2(v10, v11);
                } else {
                    size_t base = (((size_t)(b_ * HH + h) * DKK) + dk) * SS + s;
                    float vv[4] = {v00, v01, v10, v11};
                    size_t off[4] = {base, base + SS, base + 8, base + SS + 8};
#pragma unroll
                    for (int e = 0; e < 4; ++e) {
                        __nv_bfloat16 hh = __float2bfloat16(vv[e]);
                        g_Vthi[off[e]] = hh;
                        g_Vtlo[off[e]] = __float2bfloat16(vv[e] - __bfloat162float(hh));
                    }
                }
            } else {
                *(float2*)(outQ + (size_t)m * DD + nc) = make_float2(v00, v01);
                *(float2*)(outQ + (size_t)(m + 8) * DD + nc) = make_float2(v10, v11);
            }
        }
    }
}

// ---------------------------------------------------------------------------
// RoPE: read fp32 g_Q/g_K, rotate, write bf16 hi/lo Q/K.
// ---------------------------------------------------------------------------
__global__ __launch_bounds__(256) void rope_kernel(const int* __restrict__ pos)
{
    __shared__ float invs[32];
    if (threadIdx.x < 32)
        invs[threadIdx.x] = (float)exp(-(double)threadIdx.x * 0.28782313662425575);
    __syncthreads();

    int idx = blockIdx.x * blockDim.x + threadIdx.x;
    if (idx >= BB * HH * SS * (DKK / 2)) return;
    int i = idx & 31;
    int s = (idx >> 5) & 2047;
    int h = (idx >> 16) & 15;
    int b = idx >> 20;

    int p = pos[b * SS + s];
    float ang = (float)p * invs[i];
    float c, sn;
    sincosf(ang, &sn, &c);

    size_t base = (((size_t)(b * HH + h) * SS) + s) * DKK + 2 * i;
    float q0 = g_Q[base], q1 = g_Q[base + 1];
    float qr0 = q0 * c - q1 * sn;
    float qr1 = q0 * sn + q1 * c;
    float k0 = g_K[base], k1 = g_K[base + 1];
    float kr0 = k0 * c - k1 * sn;
    float kr1 = k0 * sn + k1 * c;

    __nv_bfloat162 qh = __floats2bfloat162_rn(qr0, qr1);
    *(uint32_t*)(g_Qhi + base) = *(uint32_t*)&qh;
    __nv_bfloat162 ql = __floats2bfloat162_rn(qr0 - __bfloat162float(qh.x),
                                              qr1 - __bfloat162float(qh.y));
    *(uint32_t*)(g_Qlo + base) = *(uint32_t*)&ql;
    __nv_bfloat162 kh = __floats2bfloat162_rn(kr0, kr1);
    *(uint32_t*)(g_Khi + base) = *(uint32_t*)&kh;
    __nv_bfloat162 kl = __floats2bfloat162_rn(kr0 - __bfloat162float(kh.x),
                                              kr1 - __bfloat162float(kh.y));
    *(uint32_t*)(g_Klo + base) = *(uint32_t*)&kl;
}

// ---------------------------------------------------------------------------
// Flash attention with HMMA (bf16x3 split for QK and PV). Unchanged from R10.
// ---------------------------------------------------------------------------
#define FL_PITCH 144
#define FL_TILE (64 * FL_PITCH)
#define FL_STAGE (4 * FL_TILE)
#define FL_SMEM (2 * FL_STAGE)

__global__ __launch_bounds__(128) void flash_mma()
{
    extern __shared__ char smem[];
    const int qt = (int)gridDim.x - 1 - (int)blockIdx.x;
    const int h = blockIdx.y;
    const int b = blockIdx.z;
    const int q0 = qt * 64;
    const int tid = threadIdx.x;
    const int lane = tid & 31;
    const int w = tid >> 5;
    const int g = lane >> 2;
    const int tg = lane & 3;

    const size_t bh = (size_t)(b * HH + h);
    const __nv_bfloat16* Qhi = g_Qhi + bh * SS * DKK;
    const __nv_bfloat16* Qlo = g_Qlo + bh * SS * DKK;
    const __nv_bfloat16* Khi = g_Khi + bh * SS * DKK;
    const __nv_bfloat16* Klo = g_Klo + bh * SS * DKK;
    const __nv_bfloat16* Vthi = g_Vthi + bh * DKK * SS;
    const __nv_bfloat16* Vtlo = g_Vtlo + bh * DKK * SS;

    const int qrow = q0 + w * 16 + g;
    uint32_t qh[4][4], ql[4][4];
#pragma unroll
    for (int kc = 0; kc < 4; ++kc) {
        size_t p0 = (size_t)qrow * DKK + kc * 16 + tg * 2;
        qh[kc][0] = *(const uint32_t*)(Qhi + p0);
        qh[kc][1] = *(const uint32_t*)(Qhi + p0 + 8 * DKK);
        qh[kc][2] = *(const uint32_t*)(Qhi + p0 + 8);
        qh[kc][3] = *(const uint32_t*)(Qhi + p0 + 8 * DKK + 8);
        ql[kc][0] = *(const uint32_t*)(Qlo + p0);
        ql[kc][1] = *(const uint32_t*)(Qlo + p0 + 8 * DKK);
        ql[kc][2] = *(const uint32_t*)(Qlo + p0 + 8);
        ql[kc][3] = *(const uint32_t*)(Qlo + p0 + 8 * DKK + 8);
    }

    auto load_stage = [&](int st, int t) {
        const int j0 = t * 64;
        char* sb = smem + st * FL_STAGE;
#pragma unroll
        for (int i = 0; i < 4; ++i) {
            int v = i * 128 + tid;
            int r = v >> 3, c = v & 7;
            uint32_t d = s2u(sb + r * FL_PITCH + c * 16);
            size_t ksrc = (size_t)(j0 + r) * DKK + c * 8;
            cp16(d, Khi + ksrc);
            cp16(d + FL_TILE, Klo + ksrc);
            size_t vsrc = (size_t)r * SS + j0 + c * 8;
            cp16(d + 2 * FL_TILE, Vthi + vsrc);
            cp16(d + 3 * FL_TILE, Vtlo + vsrc);
        }
    };

    float o[8][4] = {};
    float m_g = -1e30f, m_g8 = -1e30f;
    float l_g = 0.f, l_g8 = 0.f;

    const int nT = qt + 1;
    load_stage(0, 0); CP_COMMIT();
    if (nT > 1) load_stage(1, 1);
    CP_COMMIT();

    for (int t = 0; t < nT; ++t) {
        const int st = t & 1;
        CP_WAIT1();
        __syncthreads();

        const char* sK  = smem + st * FL_STAGE;
        const char* sKl = sK + FL_TILE;
        const char* sV  = sK + 2 * FL_TILE;
        const char* sVl = sK + 3 * FL_TILE;
        const int j0 = t * 64;

        float s[8][4] = {};
#pragma unroll
        for (int kc = 0; kc < 4; ++kc) {
            const int kb = kc * 32 + tg * 4;
            uint32_t kh[8][2], kl[8][2];
#pragma unroll
            for (int nf = 0; nf < 8; ++nf) {
                const char* p = sK + (nf * 8 + g) * FL_PITCH + kb;
                kh[nf][0] = *(const uint32_t*)p;
                kh[nf][1] = *(const uint32_t*)(p + 16);
                const char* p2 = sKl + (nf * 8 + g) * FL_PITCH + kb;
                kl[nf][0] = *(const uint32_t*)p2;
                kl[nf][1] = *(const uint32_t*)(p2 + 16);
            }
#pragma unroll
            for (int nf = 0; nf < 8; ++nf) {
                mma16816(s[nf], qh[kc], kh[nf]);
                mma16816(s[nf], qh[kc], kl[nf]);
                mma16816(s[nf], ql[kc], kh[nf]);
            }
        }

        const bool diag = (t == qt);
#pragma unroll
        for (int nf = 0; nf < 8; ++nf) {
#pragma unroll
            for (int e = 0; e < 4; ++e) {
                float v = s[nf][e] * SCALE;
                if (diag) {
                    int col = j0 + nf * 8 + tg * 2 + (e & 1);
                    int row = qrow + ((e >> 1) << 3);
                    if (col > row) v = -1e30f;
                }
                s[nf][e] = v;
            }
        }

        float tm_g = -1e30f, tm_g8 = -1e30f;
#pragma unroll
        for (int nf = 0; nf < 8; ++nf) {
            tm_g  = fmaxf(tm_g,  fmaxf(s[nf][0], s[nf][1]));
            tm_g8 = fmaxf(tm_g8, fmaxf(s[nf][2], s[nf][3]));
        }
        tm_g  = fmaxf(tm_g,  __shfl_xor_sync(0xffffffffu, tm_g, 1));
        tm_g  = fmaxf(tm_g,  __shfl_xor_sync(0xffffffffu, tm_g, 2));
        tm_g8 = fmaxf(tm_g8, __shfl_xor_sync(0xffffffffu, tm_g8, 1));
        tm_g8 = fmaxf(tm_g8, __shfl_xor_sync(0xffffffffu, tm_g8, 2));

        float mn_g = fmaxf(m_g, tm_g);
        float mn_g8 = fmaxf(m_g8, tm_g8);
        float alpha_g = expf(m_g - mn_g);
        float alpha_g8 = expf(m_g8 - mn_g8);
        m_g = mn_g; m_g8 = mn_g8;

        float sum_g = 0.f, sum_g8 = 0.f;
#pragma unroll
        for (int nf = 0; nf < 8; ++nf) {
            s[nf][0] = expf(s[nf][0] - mn_g);
            s[nf][1] = expf(s[nf][1] - mn_g);
            s[nf][2] = expf(s[nf][2] - mn_g8);
            s[nf][3] = expf(s[nf][3] - mn_g8);
            sum_g += s[nf][0] + s[nf][1];
            sum_g8 += s[nf][2] + s[nf][3];
        }
        sum_g  += __shfl_xor_sync(0xffffffffu, sum_g, 1);
        sum_g  += __shfl_xor_sync(0xffffffffu, sum_g, 2);
        sum_g8 += __shfl_xor_sync(0xffffffffu, sum_g8, 1);
        sum_g8 += __shfl_xor_sync(0xffffffffu, sum_g8, 2);
        l_g = l_g * alpha_g + sum_g;
        l_g8 = l_g8 * alpha_g8 + sum_g8;

#pragma unroll
        for (int nf = 0; nf < 8; ++nf) {
            o[nf][0] *= alpha_g;
            o[nf][1] *= alpha_g;
            o[nf][2] *= alpha_g8;
            o[nf][3] *= alpha_g8;
        }

#pragma unroll
        for (int kc = 0; kc < 4; ++kc) {
            uint32_t ph[4], pl[4];
            {
                const float* s0 = s[2 * kc];
                const float* s1 = s[2 * kc + 1];
                float h0 = __bfloat162float(__float2bfloat16(s0[0]));
                float h1 = __bfloat162float(__float2bfloat16(s0[1]));
                float h2 = __bfloat162float(__float2bfloat16(s0[2]));
                float h3 = __bfloat162float(__float2bfloat16(s0[3]));
                float h4 = __bfloat162float(__float2bfloat16(s1[0]));
                float h5 = __bfloat162float(__float2bfloat16(s1[1]));
                float h6 = __bfloat162float(__float2bfloat16(s1[2]));
                float h7 = __bfloat162float(__float2bfloat16(s1[3]));
                ph[0] = pack_bf2(h0, h1);
                ph[1] = pack_bf2(h2, h3);
                ph[2] = pack_bf2(h4, h5);
                ph[3] = pack_bf2(h6, h7);
                pl[0] = pack_bf2(s0[0] - h0, s0[1] - h1);
                pl[1] = pack_bf2(s0[2] - h2, s0[3] - h3);
                pl[2] = pack_bf2(s1[0] - h4, s1[1] - h5);
                pl[3] = pack_bf2(s1[2] - h6, s1[3] - h7);
            }
            const int kb = kc * 32 + tg * 4;
            uint32_t vh[8][2], vl[8][2];
#pragma unroll
            for (int nf = 0; nf < 8; ++nf) {
                const char* p = sV + (nf * 8 + g) * FL_PITCH + kb;
                vh[nf][0] = *(const uint32_t*)p;
                vh[nf][1] = *(const uint32_t*)(p + 16);
                const char* p2 = sVl + (nf * 8 + g) * FL_PITCH + kb;
                vl[nf][0] = *(const uint32_t*)p2;
                vl[nf][1] = *(const uint32_t*)(p2 + 16);
            }
#pragma unroll
            for (int nf = 0; nf < 8; ++nf) {
                mma16816(o[nf], ph, vh[nf]);
                mma16816(o[nf], ph, vl[nf]);
                mma16816(o[nf], pl, vh[nf]);
            }
        }

        __syncthreads();
        if (t + 2 < nT) load_stage(st, t + 2);
        CP_COMMIT();
    }

    const float inv_g = 1.0f / l_g;
    const float inv_g8 = 1.0f / l_g8;
#pragma unroll
    for (int nf = 0; nf < 8; ++nf) {
        const int col = h * DKK + nf * 8 + tg * 2;
        {
            float v0 = o[nf][0] * inv_g, v1 = o[nf][1] * inv_g;
            size_t addr = ((size_t)b * SS + qrow) * DD + col;
            __nv_bfloat162 hh = __floats2bfloat162_rn(v0, v1);
            *(uint32_t*)(g_ahi + addr) = *(uint32_t*)&hh;
            __nv_bfloat162 ll = __floats2bfloat162_rn(v0 - __bfloat162float(hh.x),
                                                      v1 - __bfloat162float(hh.y));
            *(uint32_t*)(g_alo + addr) = *(uint32_t*)&ll;
        }
        {
            float v0 = o[nf][2] * inv_g8, v1 = o[nf][3] * inv_g8;
            size_t addr = ((size_t)b * SS + qrow + 8) * DD + col;
            __nv_bfloat162 hh = __floats2bfloat162_rn(v0, v1);
            *(uint32_t*)(g_ahi + addr) = *(uint32_t*)&hh;
            __nv_bfloat162 ll = __floats2bfloat162_rn(v0 - __bfloat162float(hh.x),
                                                      v1 - __bfloat162float(hh.y));
            *(uint32_t*)(g_alo + addr) = *(uint32_t*)&ll;
        }
    }
}

// ---------------------------------------------------------------------------
extern "C" void kernel_launch(void* const* d_in, const int* in_sizes, int n_in,
                              void* d_out, int out_size)
{
    const float* x  = (const float*)d_in[0];
    const int*   tp = (const int*)d_in[1];
    const float* Wq = (const float*)d_in[2];
    const float* bq = (const float*)d_in[3];
    const float* Wk = (const float*)d_in[4];
    const float* bk = (const float*)d_in[5];
    const float* Wv = (const float*)d_in[6];
    const float* bv = (const float*)d_in[7];
    const float* Wo = (const float*)d_in[8];
    const float* bo = (const float*)d_in[9];
    float* out = (float*)d_out;

    float *Qp, *Kp;
    __nv_bfloat16 *xhi, *xlo, *ahi, *alo, *whi, *wlo;
    cudaGetSymbolAddress((void**)&Qp, g_Q);
    cudaGetSymbolAddress((void**)&Kp, g_K);
    cudaGetSymbolAddress((void**)&xhi, g_xhi);
    cudaGetSymbolAddress((void**)&xlo, g_xlo);
    cudaGetSymbolAddress((void**)&ahi, g_ahi);
    cudaGetSymbolAddress((void**)&alo, g_alo);
    cudaGetSymbolAddress((void**)&whi, g_whi);
    cudaGetSymbolAddress((void**)&wlo, g_wlo);

    static int attr_set = 0;
    if (!attr_set) {
        cudaFuncSetAttribute(mma_gemm<true>,
                             cudaFuncAttributeMaxDynamicSharedMemorySize, GEMM_SMEM);
        cudaFuncSetAttribute(mma_gemm<false>,
                             cudaFuncAttributeMaxDynamicSharedMemorySize, GEMM_SMEM);
        cudaFuncSetAttribute(flash_mma,
                             cudaFuncAttributeMaxDynamicSharedMemorySize, FL_SMEM);
        attr_set = 1;
    }

    const int nX = MM * DD;
    dim3 bW(32, 8);

    convert_hl<<<nX / 4 / 256, 256>>>(x, xhi, xlo, nX);
    convert_w4_t<<<dim3(32, 32, 4), bW>>>(Wq, Wk, Wv, Wo);

    // Fused QKV projection: N=3072, 768 CTAs (~2.6 waves at 2 CTAs/SM)
    dim3 gQKV(3 * DD / 128, MM / 128);  // (24, 32)
    mma_gemm<true><<<gQKV, 256, GEMM_SMEM>>>(xhi, xlo, whi, wlo,
                                             bq, bk, bv, Qp, Kp);

    int ropeThreads = BB * HH * SS * (DKK / 2);
    rope_kernel<<<(ropeThreads + 255) / 256, 256>>>(tp);

    dim3 gFlash(SS / 64, HH, BB);
    flash_mma<<<gFlash, 128, FL_SMEM>>>();

    // O projection (weight section 3)
    dim3 gO(DD / 128, MM / 128);  // (8, 32)
    mma_gemm<false><<<gO, 256, GEMM_SMEM>>>(ahi, alo,
                                            whi + (size_t)3 * DD * DD,
                                            wlo + (size_t)3 * DD * DD,
                                            bo, bo, bo, out, nullptr);
}